// round 1
// baseline (speedup 1.0000x reference)
#include <cuda_runtime.h>
#include <math.h>

#define DIM   256
#define TSEQ  4096
#define BATCH 32
#define NH    4
#define HD    64

// ---------------- scratch (device globals; no allocation APIs) ----------------
__device__ float g_q[(size_t)BATCH * TSEQ * DIM];
__device__ float g_k[(size_t)BATCH * TSEQ * DIM];
__device__ float g_v[(size_t)BATCH * TSEQ * DIM];
__device__ float g_acc[BATCH * DIM];

// ---------------- zero accumulator ----------------
__global__ void zero_acc_kernel() {
    int i = blockIdx.x * blockDim.x + threadIdx.x;
    if (i < BATCH * DIM) g_acc[i] = 0.0f;
}

// ---------------- QKV GEMM: C = A[131072,256] @ W[256,256] + bias ----------------
#define BM 128
#define BN 128
#define BK 8

__global__ __launch_bounds__(256) void qkv_gemm_kernel(
    const float* __restrict__ A,
    const float* __restrict__ Wq, const float* __restrict__ bq,
    const float* __restrict__ Wk, const float* __restrict__ bk,
    const float* __restrict__ Wv, const float* __restrict__ bv)
{
    const float* W;
    const float* bias;
    float* C;
    if (blockIdx.z == 0)      { W = Wq; bias = bq; C = g_q; }
    else if (blockIdx.z == 1) { W = Wk; bias = bk; C = g_k; }
    else                      { W = Wv; bias = bv; C = g_v; }

    __shared__ float As[BK][BM];
    __shared__ float Bs[BK][BN];

    const int tid = threadIdx.x;
    const int tx = tid & 15;        // 0..15 -> 8 output cols each
    const int ty = tid >> 4;        // 0..15 -> 8 output rows each

    const long mbase = (long)blockIdx.x * BM;
    const int  nbase = blockIdx.y * BN;

    const int arow = tid >> 1;          // 0..127
    const int acol = (tid & 1) * 4;     // 0 or 4
    const int brow = tid >> 5;          // 0..7
    const int bcol = (tid & 31) * 4;    // 0..124

    float acc[8][8];
    #pragma unroll
    for (int m = 0; m < 8; m++)
        #pragma unroll
        for (int n = 0; n < 8; n++) acc[m][n] = 0.0f;

    for (int kt = 0; kt < DIM; kt += BK) {
        float4 av = *(const float4*)&A[(mbase + arow) * DIM + kt + acol];
        As[acol + 0][arow] = av.x;
        As[acol + 1][arow] = av.y;
        As[acol + 2][arow] = av.z;
        As[acol + 3][arow] = av.w;
        *(float4*)&Bs[brow][bcol] =
            *(const float4*)&W[(kt + brow) * DIM + nbase + bcol];
        __syncthreads();

        #pragma unroll
        for (int kk = 0; kk < BK; kk++) {
            float ra[8], rb[8];
            *(float4*)&ra[0] = *(const float4*)&As[kk][ty * 8];
            *(float4*)&ra[4] = *(const float4*)&As[kk][ty * 8 + 4];
            *(float4*)&rb[0] = *(const float4*)&Bs[kk][tx * 8];
            *(float4*)&rb[4] = *(const float4*)&Bs[kk][tx * 8 + 4];
            #pragma unroll
            for (int m = 0; m < 8; m++)
                #pragma unroll
                for (int n = 0; n < 8; n++)
                    acc[m][n] += ra[m] * rb[n];
        }
        __syncthreads();
    }

    #pragma unroll
    for (int m = 0; m < 8; m++) {
        long row = mbase + ty * 8 + m;
        #pragma unroll
        for (int n4 = 0; n4 < 8; n4 += 4) {
            int col = nbase + tx * 8 + n4;
            float4 o;
            o.x = acc[m][n4 + 0] + bias[col + 0];
            o.y = acc[m][n4 + 1] + bias[col + 1];
            o.z = acc[m][n4 + 2] + bias[col + 2];
            o.w = acc[m][n4 + 3] + bias[col + 3];
            *(float4*)&C[row * DIM + col] = o;
        }
    }
}

// ---------------- fused pool + window attention + gelu + weighted accumulate ----------------
// Block: 8 windows (32 pooled rows) of one batch. 128 threads = 4 warps (one per head).
// Lane mapping within warp: wl = lane>>2 (window 0..7), i = lane&3 (query row in window).
#define SM_STRIDE 257
#define ROWS_PB   32   // 8 windows * 4

template <int KSIZE>
__global__ __launch_bounds__(128) void attn_kernel(int Ts)
{
    extern __shared__ float sm[];
    float* qs    = sm;
    float* ksm   = sm + ROWS_PB * SM_STRIDE;
    float* vsm   = sm + 2 * ROWS_PB * SM_STRIDE;
    float* accsm = sm + 3 * ROWS_PB * SM_STRIDE;

    const int tid = threadIdx.x;
    const int b   = blockIdx.y;
    const int l0  = blockIdx.x * ROWS_PB;   // first pooled row of this block
    const long base = (long)b * TSEQ * DIM;

    for (int idx = tid; idx < DIM; idx += 128) accsm[idx] = 0.0f;

    // fill smem with pooled q/k/v (zeros for padded rows)
    for (int idx = tid; idx < ROWS_PB * DIM; idx += 128) {
        int r = idx >> 8;
        int d = idx & 255;
        int l = l0 + r;
        float fq = 0.0f, fk = 0.0f, fv = 0.0f;
        if (l < Ts) {
            if (KSIZE == 1) {
                long off = base + (long)l * DIM + d;
                fq = g_q[off]; fk = g_k[off]; fv = g_v[off];
            } else {
                #pragma unroll
                for (int rr = 0; rr < KSIZE; rr++) {
                    int o = l * KSIZE + rr - KSIZE / 2;
                    if (o < 0) o = -o;
                    if (o >= TSEQ) o = 2 * TSEQ - 2 - o;
                    long off = base + (long)o * DIM + d;
                    fq += g_q[off]; fk += g_k[off]; fv += g_v[off];
                }
                const float inv = 1.0f / (float)KSIZE;
                fq *= inv; fk *= inv; fv *= inv;
            }
        }
        int so = r * SM_STRIDE + d;
        qs[so] = fq; ksm[so] = fk; vsm[so] = fv;
    }
    __syncthreads();

    const int lane = tid & 31;
    const int h    = tid >> 5;       // head = warp id
    const int wl   = lane >> 2;      // local window 0..7
    const int i    = lane & 3;       // query row within window
    const int hb   = h * HD;

    const float* qp = &qs[(wl * 4 + i) * SM_STRIDE + hb];

    float s[4];
    #pragma unroll
    for (int j = 0; j < 4; j++) {
        const float* kp = &ksm[(wl * 4 + j) * SM_STRIDE + hb];
        float a = 0.0f;
        #pragma unroll
        for (int d = 0; d < HD; d++) a += qp[d] * kp[d];
        s[j] = a * 0.125f;
    }
    float mx = fmaxf(fmaxf(s[0], s[1]), fmaxf(s[2], s[3]));
    float e0 = expf(s[0] - mx), e1 = expf(s[1] - mx);
    float e2 = expf(s[2] - mx), e3 = expf(s[3] - mx);
    float inv = 1.0f / (e0 + e1 + e2 + e3);
    float a0 = e0 * inv, a1 = e1 * inv, a2 = e2 * inv, a3 = e3 * inv;

    // nearest-upsample count weight for this pooled row
    int jglob = l0 + wl * 4 + i;
    float wgt = 0.0f;
    if (jglob < Ts) {
        int c = (TSEQ * (jglob + 1) + Ts - 1) / Ts - (TSEQ * jglob + Ts - 1) / Ts;
        wgt = (float)c;
    }

    const float* v0 = &vsm[(wl * 4 + 0) * SM_STRIDE + hb];
    const float* v1 = &vsm[(wl * 4 + 1) * SM_STRIDE + hb];
    const float* v2 = &vsm[(wl * 4 + 2) * SM_STRIDE + hb];
    const float* v3 = &vsm[(wl * 4 + 3) * SM_STRIDE + hb];

    for (int d = 0; d < HD; d++) {
        float o = a0 * v0[d] + a1 * v1[d] + a2 * v2[d] + a3 * v3[d];
        float g = 0.5f * o * (1.0f + erff(o * 0.70710678118f));
        float c = wgt * g;
        #pragma unroll
        for (int off = 16; off; off >>= 1)
            c += __shfl_xor_sync(0xffffffffu, c, off);
        if (lane == 0) accsm[hb + d] += c;   // one warp owns each head's 64 dims
    }
    __syncthreads();

    for (int idx = tid; idx < DIM; idx += 128)
        atomicAdd(&g_acc[b * DIM + idx], accsm[idx]);
}

// ---------------- classifier: mean -> Wp -> relu Wc1 -> Wc2 ----------------
__global__ __launch_bounds__(256) void classifier_kernel(
    const float* __restrict__ Wp,  const float* __restrict__ bp,
    const float* __restrict__ Wc1, const float* __restrict__ bc1,
    const float* __restrict__ Wc2, const float* __restrict__ bc2,
    float* __restrict__ out)
{
    __shared__ float m[DIM], fm[DIM], hbuf[DIM];
    const int b = blockIdx.x;
    const int t = threadIdx.x;

    m[t] = g_acc[b * DIM + t] * (1.0f / (float)TSEQ);
    __syncthreads();

    float a = bp[t];
    for (int k = 0; k < DIM; k++) a += m[k] * Wp[k * DIM + t];
    fm[t] = a;
    __syncthreads();

    float a2 = bc1[t];
    for (int k = 0; k < DIM; k++) a2 += fm[k] * Wc1[k * DIM + t];
    hbuf[t] = fmaxf(a2, 0.0f);
    __syncthreads();

    if (t < 7) {
        float a3 = bc2[t];
        for (int k = 0; k < DIM; k++) a3 += hbuf[k] * Wc2[k * 7 + t];
        out[b * 7 + t] = a3;
    }
}

// ---------------- launch ----------------
extern "C" void kernel_launch(void* const* d_in, const int* in_sizes, int n_in,
                              void* d_out, int out_size)
{
    const float* x   = (const float*)d_in[0];
    const float* Wq  = (const float*)d_in[1];
    const float* bq  = (const float*)d_in[2];
    const float* Wk  = (const float*)d_in[3];
    const float* bk  = (const float*)d_in[4];
    const float* Wv  = (const float*)d_in[5];
    const float* bv  = (const float*)d_in[6];
    const float* Wp  = (const float*)d_in[7];
    const float* bp  = (const float*)d_in[8];
    const float* Wc1 = (const float*)d_in[9];
    const float* bc1 = (const float*)d_in[10];
    const float* Wc2 = (const float*)d_in[11];
    const float* bc2 = (const float*)d_in[12];
    float* out = (float*)d_out;

    const int smem_bytes = (3 * ROWS_PB * SM_STRIDE + DIM) * (int)sizeof(float);
    cudaFuncSetAttribute(attn_kernel<1>, cudaFuncAttributeMaxDynamicSharedMemorySize, smem_bytes);
    cudaFuncSetAttribute(attn_kernel<2>, cudaFuncAttributeMaxDynamicSharedMemorySize, smem_bytes);
    cudaFuncSetAttribute(attn_kernel<4>, cudaFuncAttributeMaxDynamicSharedMemorySize, smem_bytes);

    zero_acc_kernel<<<(BATCH * DIM + 255) / 256, 256>>>();

    dim3 ggrid((BATCH * TSEQ) / BM, DIM / BN, 3);
    qkv_gemm_kernel<<<ggrid, 256>>>(x, Wq, bq, Wk, bk, Wv, bv);

    // scale 1: Ts=4096, nw=1024 -> 128 blocks of 8 windows
    attn_kernel<1><<<dim3(128, BATCH), 128, smem_bytes>>>(4096);
    // scale 2: Ts=2049, Tp=2052, nw=513 -> 65 blocks
    attn_kernel<2><<<dim3(65, BATCH), 128, smem_bytes>>>(2049);
    // scale 3: Ts=1025, Tp=1028, nw=257 -> 33 blocks
    attn_kernel<4><<<dim3(33, BATCH), 128, smem_bytes>>>(1025);

    classifier_kernel<<<BATCH, 256>>>(Wp, bp, Wc1, bc1, Wc2, bc2, out);
}

// round 4
// speedup vs baseline: 1.2869x; 1.2869x over previous
#include <cuda_runtime.h>
#include <cuda_bf16.h>
#include <math.h>

#define DIM   256
#define TSEQ  4096
#define BATCH 32
#define HD    64
#define MTOT  (BATCH * TSEQ)   // 131072

// ---------------- device scratch ----------------
__device__ float g_q[(size_t)MTOT * DIM];
__device__ float g_k[(size_t)MTOT * DIM];
__device__ float g_v[(size_t)MTOT * DIM];
__device__ __nv_bfloat16 g_xh[(size_t)MTOT * DIM];
__device__ __nv_bfloat16 g_xl[(size_t)MTOT * DIM];
__device__ __nv_bfloat16 g_wh[3][DIM * DIM];
__device__ __nv_bfloat16 g_wl[3][DIM * DIM];
__device__ float g_acc[BATCH * DIM];

__global__ void zero_acc_kernel() {
    int i = blockIdx.x * blockDim.x + threadIdx.x;
    if (i < BATCH * DIM) g_acc[i] = 0.0f;
}

// ---------------- asm helpers (scalar-operand style) ----------------
__device__ __forceinline__ void cp_async16(unsigned dst, const void* src) {
    asm volatile("cp.async.cg.shared.global [%0], [%1], 16;" :: "r"(dst), "l"(src));
}
__device__ __forceinline__ void cp_commit() {
    asm volatile("cp.async.commit_group;");
}
__device__ __forceinline__ void cp_wait1() {
    asm volatile("cp.async.wait_group 1;");
}
__device__ __forceinline__ void cp_wait0() {
    asm volatile("cp.async.wait_group 0;");
}
__device__ __forceinline__ void ldsm_x4(unsigned& r0, unsigned& r1, unsigned& r2, unsigned& r3,
                                        unsigned addr) {
    asm volatile("ldmatrix.sync.aligned.m8n8.x4.shared.b16 {%0,%1,%2,%3},[%4];"
                 : "=r"(r0), "=r"(r1), "=r"(r2), "=r"(r3) : "r"(addr));
}
__device__ __forceinline__ void ldsm_x4_trans(unsigned& r0, unsigned& r1, unsigned& r2, unsigned& r3,
                                              unsigned addr) {
    asm volatile("ldmatrix.sync.aligned.m8n8.x4.trans.shared.b16 {%0,%1,%2,%3},[%4];"
                 : "=r"(r0), "=r"(r1), "=r"(r2), "=r"(r3) : "r"(addr));
}
__device__ __forceinline__ void mma_bf16(float* D, unsigned a0, unsigned a1, unsigned a2, unsigned a3,
                                         unsigned b0, unsigned b1) {
    asm volatile("mma.sync.aligned.m16n8k16.row.col.f32.bf16.bf16.f32 "
                 "{%0,%1,%2,%3},{%4,%5,%6,%7},{%8,%9},{%0,%1,%2,%3};"
                 : "+f"(D[0]), "+f"(D[1]), "+f"(D[2]), "+f"(D[3])
                 : "r"(a0), "r"(a1), "r"(a2), "r"(a3), "r"(b0), "r"(b1));
}

// ---------------- fp32 -> bf16 hi/lo split ----------------
__global__ __launch_bounds__(256) void cvt_x_kernel(const float* __restrict__ x) {
    size_t i = ((size_t)blockIdx.x * 256 + threadIdx.x) * 4;
    float4 v = *(const float4*)(x + i);
    float f[4] = {v.x, v.y, v.z, v.w};
    unsigned short hs[4], ls[4];
    #pragma unroll
    for (int j = 0; j < 4; j++) {
        __nv_bfloat16 h = __float2bfloat16(f[j]);
        float hf = __bfloat162float(h);
        __nv_bfloat16 l = __float2bfloat16(f[j] - hf);
        hs[j] = __bfloat16_as_ushort(h);
        ls[j] = __bfloat16_as_ushort(l);
    }
    uint2 ph, pl;
    ph.x = (unsigned)hs[0] | ((unsigned)hs[1] << 16);
    ph.y = (unsigned)hs[2] | ((unsigned)hs[3] << 16);
    pl.x = (unsigned)ls[0] | ((unsigned)ls[1] << 16);
    pl.y = (unsigned)ls[2] | ((unsigned)ls[3] << 16);
    *(uint2*)(g_xh + i) = ph;
    *(uint2*)(g_xl + i) = pl;
}

__global__ __launch_bounds__(256) void cvt_w_kernel(const float* __restrict__ Wq,
                                                    const float* __restrict__ Wk,
                                                    const float* __restrict__ Wv) {
    int i = (blockIdx.x * 256 + threadIdx.x) * 4;
    if (i >= 3 * DIM * DIM) return;
    int z = i >> 16;
    int o = i & 65535;
    const float* W = (z == 0) ? Wq : (z == 1) ? Wk : Wv;
    float4 v = *(const float4*)(W + o);
    float f[4] = {v.x, v.y, v.z, v.w};
    unsigned short hs[4], ls[4];
    #pragma unroll
    for (int j = 0; j < 4; j++) {
        __nv_bfloat16 h = __float2bfloat16(f[j]);
        float hf = __bfloat162float(h);
        __nv_bfloat16 l = __float2bfloat16(f[j] - hf);
        hs[j] = __bfloat16_as_ushort(h);
        ls[j] = __bfloat16_as_ushort(l);
    }
    uint2 ph, pl;
    ph.x = (unsigned)hs[0] | ((unsigned)hs[1] << 16);
    ph.y = (unsigned)hs[2] | ((unsigned)hs[3] << 16);
    pl.x = (unsigned)ls[0] | ((unsigned)ls[1] << 16);
    pl.y = (unsigned)ls[2] | ((unsigned)ls[3] << 16);
    *(uint2*)(&g_wh[z][o]) = ph;
    *(uint2*)(&g_wl[z][o]) = pl;
}

// ---------------- tensor-core GEMM: C = [Ah|Al|Ah] @ [Wh;Wh;Wl] + bias ----------------
#define GM 128
#define GK 64
#define ASTRIDE 72    // halfwords (144B = 9*16B)
#define BSTRIDE 264   // halfwords (528B = 33*16B)

__device__ __forceinline__ void gemm_load_chunk(int s, int buf, int tid, long mbase,
                                                const __nv_bfloat16* Whz,
                                                const __nv_bfloat16* Wlz,
                                                __nv_bfloat16* As, __nv_bfloat16* Bs)
{
    int p = s >> 2;
    const __nv_bfloat16* A = (p == 1) ? g_xl : g_xh;
    const __nv_bfloat16* W = (p == 2) ? Wlz : Whz;
    int kc = (s & 3) * GK;
    unsigned asm_base = (unsigned)__cvta_generic_to_shared(As + buf * 128 * ASTRIDE);
    unsigned bsm_base = (unsigned)__cvta_generic_to_shared(Bs + buf * 64 * BSTRIDE);
    #pragma unroll
    for (int i = 0; i < 2; i++) {                 // A: 1024 x 16B
        int lin = tid + i * 512;
        int r = lin >> 3, c8 = lin & 7;
        unsigned dst = asm_base + (unsigned)(r * ASTRIDE + c8 * 8) * 2u;
        cp_async16(dst, (const void*)(A + (mbase + r) * DIM + kc + c8 * 8));
    }
    #pragma unroll
    for (int i = 0; i < 4; i++) {                 // B: 2048 x 16B
        int lin = tid + i * 512;
        int r = lin >> 5, c8 = lin & 31;
        unsigned dst = bsm_base + (unsigned)(r * BSTRIDE + c8 * 8) * 2u;
        cp_async16(dst, (const void*)(W + (kc + r) * DIM + c8 * 8));
    }
    cp_commit();
}

__global__ __launch_bounds__(512, 1) void gemm_qkv_kernel(
    const float* __restrict__ bq, const float* __restrict__ bk, const float* __restrict__ bv)
{
    extern __shared__ __nv_bfloat16 sm[];
    __nv_bfloat16* As = sm;                        // 2 * 128 * ASTRIDE
    __nv_bfloat16* Bs = sm + 2 * 128 * ASTRIDE;    // 2 * 64  * BSTRIDE

    const int z = blockIdx.x;
    const long mbase = (long)blockIdx.y * GM;
    const float* bias = (z == 0) ? bq : (z == 1) ? bk : bv;
    float* C = (z == 0) ? g_q : (z == 1) ? g_k : g_v;
    const __nv_bfloat16* Whz = g_wh[z];
    const __nv_bfloat16* Wlz = g_wl[z];

    const int tid = threadIdx.x;
    const int warp = tid >> 5, lane = tid & 31;
    const int wm = (warp >> 2) * 32;   // 0..96
    const int wn = (warp & 3) * 64;    // 0..192

    float acc[2][8][4];
    #pragma unroll
    for (int i = 0; i < 2; i++)
        #pragma unroll
        for (int j = 0; j < 8; j++)
            #pragma unroll
            for (int c = 0; c < 4; c++) acc[i][j][c] = 0.0f;

    gemm_load_chunk(0, 0, tid, mbase, Whz, Wlz, As, Bs);
    int buf = 0;
    for (int s = 0; s < 12; s++) {
        if (s + 1 < 12) {
            gemm_load_chunk(s + 1, buf ^ 1, tid, mbase, Whz, Wlz, As, Bs);
            cp_wait1();
        } else {
            cp_wait0();
        }
        __syncthreads();

        unsigned a_base = (unsigned)__cvta_generic_to_shared(As + buf * 128 * ASTRIDE);
        unsigned b_base = (unsigned)__cvta_generic_to_shared(Bs + buf * 64 * BSTRIDE);

        #pragma unroll
        for (int kk = 0; kk < 4; kk++) {
            unsigned af[2][4];
            #pragma unroll
            for (int mi = 0; mi < 2; mi++) {
                unsigned addr_a = a_base +
                    (unsigned)((wm + mi * 16 + (lane & 15)) * ASTRIDE + kk * 16 + (lane >> 4) * 8) * 2u;
                ldsm_x4(af[mi][0], af[mi][1], af[mi][2], af[mi][3], addr_a);
            }
            #pragma unroll
            for (int nt = 0; nt < 4; nt++) {
                unsigned b0, b1, b2, b3;
                unsigned addr_b = b_base +
                    (unsigned)((kk * 16 + (lane & 15)) * BSTRIDE + wn + nt * 16 + (lane >> 4) * 8) * 2u;
                ldsm_x4_trans(b0, b1, b2, b3, addr_b);
                #pragma unroll
                for (int mi = 0; mi < 2; mi++) {
                    mma_bf16(acc[mi][nt * 2],     af[mi][0], af[mi][1], af[mi][2], af[mi][3], b0, b1);
                    mma_bf16(acc[mi][nt * 2 + 1], af[mi][0], af[mi][1], af[mi][2], af[mi][3], b2, b3);
                }
            }
        }
        __syncthreads();
        buf ^= 1;
    }

    // epilogue
    #pragma unroll
    for (int mi = 0; mi < 2; mi++) {
        long row0 = mbase + wm + mi * 16 + (lane >> 2);
        #pragma unroll
        for (int n8 = 0; n8 < 8; n8++) {
            int col = wn + n8 * 8 + (lane & 3) * 2;
            float2 o0, o1;
            o0.x = acc[mi][n8][0] + bias[col];
            o0.y = acc[mi][n8][1] + bias[col + 1];
            o1.x = acc[mi][n8][2] + bias[col];
            o1.y = acc[mi][n8][3] + bias[col + 1];
            *(float2*)&C[row0 * DIM + col] = o0;
            *(float2*)&C[(row0 + 8) * DIM + col] = o1;
        }
    }
}

// ---------------- fused multi-scale window attention ----------------
#define SP    128
#define AROWS 131     // 3-row halo before span
#define ASTR  65

__device__ __forceinline__ int mirror_row(int o, int sbase) {
    if (o < 0) o = -o;
    if (o >= TSEQ) o = 2 * TSEQ - 2 - o;
    int r = o - sbase;
    if (r < 0) r = 0;
    if (r > AROWS - 1) r = AROWS - 1;
    return r;
}

template <int KS>
__device__ __forceinline__ void do_scale(const float* __restrict__ qs,
                                         const float* __restrict__ ks,
                                         const float* __restrict__ vs,
                                         float* __restrict__ accp,
                                         int wg, int iq, int sbase, int Ts, bool active)
{
    const int l0 = wg * 4;
    const int lq = l0 + iq;

    int rq[KS];
    #pragma unroll
    for (int rr = 0; rr < KS; rr++)
        rq[rr] = mirror_row(lq * KS + rr - KS / 2, sbase);

    int rk[4][KS];
    bool kval[4];
    #pragma unroll
    for (int j = 0; j < 4; j++) {
        kval[j] = (l0 + j) < Ts;
        #pragma unroll
        for (int rr = 0; rr < KS; rr++)
            rk[j][rr] = mirror_row((l0 + j) * KS + rr - KS / 2, sbase);
    }

    float s[4] = {0.f, 0.f, 0.f, 0.f};
    for (int d = 0; d < HD; d++) {
        float qd = 0.f;
        #pragma unroll
        for (int rr = 0; rr < KS; rr++) qd += qs[rq[rr] * ASTR + d];
        #pragma unroll
        for (int j = 0; j < 4; j++) {
            float kd = 0.f;
            #pragma unroll
            for (int rr = 0; rr < KS; rr++) kd += ks[rk[j][rr] * ASTR + d];
            s[j] += qd * kd;
        }
    }
    const float cs = 0.125f / (float)(KS * KS);
    #pragma unroll
    for (int j = 0; j < 4; j++)
        s[j] = kval[j] ? s[j] * cs : 0.0f;   // zero-padded keys score exactly 0 (matches ref)

    float mx = fmaxf(fmaxf(s[0], s[1]), fmaxf(s[2], s[3]));
    float e0 = expf(s[0] - mx), e1 = expf(s[1] - mx);
    float e2 = expf(s[2] - mx), e3 = expf(s[3] - mx);
    float inv = 1.0f / (e0 + e1 + e2 + e3);
    float a[4];
    a[0] = kval[0] ? e0 * inv : 0.f;
    a[1] = kval[1] ? e1 * inv : 0.f;
    a[2] = kval[2] ? e2 * inv : 0.f;
    a[3] = kval[3] ? e3 * inv : 0.f;
    const float invK = 1.0f / (float)KS;
    #pragma unroll
    for (int j = 0; j < 4; j++) a[j] *= invK;

    float wgt = 0.0f;
    if (active && lq < Ts) {
        int cnt = (TSEQ * (lq + 1) + Ts - 1) / Ts - (TSEQ * lq + Ts - 1) / Ts;
        wgt = (float)cnt;
    }

    const int lane = threadIdx.x & 31;
    for (int d = 0; d < HD; d++) {
        float o = 0.f;
        #pragma unroll
        for (int j = 0; j < 4; j++) {
            float vv = 0.f;
            #pragma unroll
            for (int rr = 0; rr < KS; rr++) vv += vs[rk[j][rr] * ASTR + d];
            o += a[j] * vv;
        }
        float g = 0.5f * o * (1.0f + erff(o * 0.70710678118f));
        float c = wgt * g;
        #pragma unroll
        for (int off = 16; off; off >>= 1)
            c += __shfl_xor_sync(0xffffffffu, c, off);
        if (lane == 0) accp[d] += c;
    }
}

__global__ __launch_bounds__(256) void attn_fused_kernel()
{
    extern __shared__ float smf[];
    float* qs   = smf;
    float* ksm  = smf + AROWS * ASTR;
    float* vsm  = smf + 2 * AROWS * ASTR;
    float* accw = smf + 3 * AROWS * ASTR;   // [8][64]

    const int tid = threadIdx.x;
    const int bi = blockIdx.x;    // span index, 0..32
    const int b  = blockIdx.y;
    const int h  = blockIdx.z;
    const int sbase = bi * SP - 3;
    const long gbase = (long)b * TSEQ * DIM + h * HD;

    for (int idx = tid; idx < 8 * HD; idx += 256) accw[idx] = 0.0f;

    const float* gq = g_q + gbase;
    const float* gk = g_k + gbase;
    const float* gv = g_v + gbase;

    for (int idx = tid; idx < 3 * AROWS * 16; idx += 256) {
        int t = idx / (AROWS * 16);
        int rem = idx - t * (AROWS * 16);
        int r = rem >> 4;
        int c4 = (rem & 15) * 4;
        int o = sbase + r;
        if (o < 0) o = -o;
        if (o >= TSEQ) o = 2 * TSEQ - 2 - o;
        const float* src = (t == 0 ? gq : t == 1 ? gk : gv) + (long)o * DIM + c4;
        float4 v = *(const float4*)src;
        float* dst = (t == 0 ? qs : t == 1 ? ksm : vsm) + r * ASTR + c4;
        dst[0] = v.x; dst[1] = v.y; dst[2] = v.z; dst[3] = v.w;
    }
    __syncthreads();

    const int warp = tid >> 5;
    const int lane = tid & 31;
    const int wl = lane >> 2;
    const int iq = lane & 3;
    float* accp = accw + warp * HD;

    if (warp < 4) {
        int wg = bi * 32 + warp * 8 + wl;
        do_scale<1>(qs, ksm, vsm, accp, wg, iq, sbase, TSEQ, true);
    } else if (warp < 6) {
        int wg = bi * 16 + (warp - 4) * 8 + wl;
        do_scale<2>(qs, ksm, vsm, accp, wg, iq, sbase, 2049, true);
    } else {
        int wg = bi * 8 + (warp - 6) * 4 + wl;
        do_scale<4>(qs, ksm, vsm, accp, wg, iq, sbase, 1025, wl < 4);
    }
    __syncthreads();

    if (tid < HD) {
        float ssum = 0.f;
        #pragma unroll
        for (int w = 0; w < 8; w++) ssum += accw[w * HD + tid];
        atomicAdd(&g_acc[b * DIM + h * HD + tid], ssum);
    }
}

// ---------------- classifier ----------------
__global__ __launch_bounds__(256) void classifier_kernel(
    const float* __restrict__ Wp,  const float* __restrict__ bp,
    const float* __restrict__ Wc1, const float* __restrict__ bc1,
    const float* __restrict__ Wc2, const float* __restrict__ bc2,
    float* __restrict__ out)
{
    __shared__ float m[DIM], fm[DIM], hbuf[DIM];
    const int b = blockIdx.x;
    const int t = threadIdx.x;

    m[t] = g_acc[b * DIM + t] * (1.0f / (float)TSEQ);
    __syncthreads();

    float a = bp[t];
    for (int k = 0; k < DIM; k++) a += m[k] * Wp[k * DIM + t];
    fm[t] = a;
    __syncthreads();

    float a2 = bc1[t];
    for (int k = 0; k < DIM; k++) a2 += fm[k] * Wc1[k * DIM + t];
    hbuf[t] = fmaxf(a2, 0.0f);
    __syncthreads();

    if (t < 7) {
        float a3 = bc2[t];
        for (int k = 0; k < DIM; k++) a3 += hbuf[k] * Wc2[k * 7 + t];
        out[b * 7 + t] = a3;
    }
}

// ---------------- launch ----------------
extern "C" void kernel_launch(void* const* d_in, const int* in_sizes, int n_in,
                              void* d_out, int out_size)
{
    const float* x   = (const float*)d_in[0];
    const float* Wq  = (const float*)d_in[1];
    const float* bq  = (const float*)d_in[2];
    const float* Wk  = (const float*)d_in[3];
    const float* bk  = (const float*)d_in[4];
    const float* Wv  = (const float*)d_in[5];
    const float* bv  = (const float*)d_in[6];
    const float* Wp  = (const float*)d_in[7];
    const float* bp  = (const float*)d_in[8];
    const float* Wc1 = (const float*)d_in[9];
    const float* bc1 = (const float*)d_in[10];
    const float* Wc2 = (const float*)d_in[11];
    const float* bc2 = (const float*)d_in[12];
    float* out = (float*)d_out;

    const int gsmem = (2 * 128 * ASTRIDE + 2 * 64 * BSTRIDE) * (int)sizeof(__nv_bfloat16);
    const int asmem = (3 * AROWS * ASTR + 8 * HD) * (int)sizeof(float);
    cudaFuncSetAttribute(gemm_qkv_kernel, cudaFuncAttributeMaxDynamicSharedMemorySize, gsmem);
    cudaFuncSetAttribute(attn_fused_kernel, cudaFuncAttributeMaxDynamicSharedMemorySize, asmem);

    zero_acc_kernel<<<(BATCH * DIM + 255) / 256, 256>>>();

    cvt_x_kernel<<<(int)(((size_t)MTOT * DIM / 4) / 256), 256>>>(x);
    cvt_w_kernel<<<(3 * DIM * DIM / 4 + 255) / 256, 256>>>(Wq, Wk, Wv);

    gemm_qkv_kernel<<<dim3(3, MTOT / GM), 512, gsmem>>>(bq, bk, bv);

    attn_fused_kernel<<<dim3(33, BATCH, 4), 256, asmem>>>();

    classifier_kernel<<<BATCH, 256>>>(Wp, bp, Wc1, bc1, Wc2, bc2, out);
}

// round 6
// speedup vs baseline: 2.1592x; 1.6778x over previous
#include <cuda_runtime.h>
#include <cuda_bf16.h>
#include <math.h>

#define DIM   256
#define TSEQ  4096
#define BATCH 32
#define HD    64
#define MTOT  (BATCH * TSEQ)   // 131072

// ---------------- device scratch ----------------
__device__ float g_q[(size_t)MTOT * DIM];
__device__ float g_k[(size_t)MTOT * DIM];
__device__ float g_v[(size_t)MTOT * DIM];
__device__ __nv_bfloat16 g_xh[(size_t)MTOT * DIM];
__device__ __nv_bfloat16 g_xl[(size_t)MTOT * DIM];
__device__ __nv_bfloat16 g_wh[3][DIM * DIM];
__device__ __nv_bfloat16 g_wl[3][DIM * DIM];
__device__ float g_acc[BATCH * DIM];

__global__ void zero_acc_kernel() {
    int i = blockIdx.x * blockDim.x + threadIdx.x;
    if (i < BATCH * DIM) g_acc[i] = 0.0f;
}

// ---------------- asm helpers (sm_80-era only; no 'a'-gated features) ----------------
__device__ __forceinline__ void cp_async16(unsigned dst, const void* src) {
    asm volatile("cp.async.cg.shared.global [%0], [%1], 16;" :: "r"(dst), "l"(src));
}
__device__ __forceinline__ void cp_commit() { asm volatile("cp.async.commit_group;"); }
__device__ __forceinline__ void cp_wait1() { asm volatile("cp.async.wait_group 1;"); }
__device__ __forceinline__ void cp_wait0() { asm volatile("cp.async.wait_group 0;"); }
__device__ __forceinline__ void ldsm_x4(unsigned& r0, unsigned& r1, unsigned& r2, unsigned& r3,
                                        unsigned addr) {
    asm volatile("ldmatrix.sync.aligned.m8n8.x4.shared.b16 {%0,%1,%2,%3},[%4];"
                 : "=r"(r0), "=r"(r1), "=r"(r2), "=r"(r3) : "r"(addr));
}
__device__ __forceinline__ void ldsm_x4_trans(unsigned& r0, unsigned& r1, unsigned& r2, unsigned& r3,
                                              unsigned addr) {
    asm volatile("ldmatrix.sync.aligned.m8n8.x4.trans.shared.b16 {%0,%1,%2,%3},[%4];"
                 : "=r"(r0), "=r"(r1), "=r"(r2), "=r"(r3) : "r"(addr));
}
__device__ __forceinline__ void mma_bf16(float* D, unsigned a0, unsigned a1, unsigned a2, unsigned a3,
                                         unsigned b0, unsigned b1) {
    asm volatile("mma.sync.aligned.m16n8k16.row.col.f32.bf16.bf16.f32 "
                 "{%0,%1,%2,%3},{%4,%5,%6,%7},{%8,%9},{%0,%1,%2,%3};"
                 : "+f"(D[0]), "+f"(D[1]), "+f"(D[2]), "+f"(D[3])
                 : "r"(a0), "r"(a1), "r"(a2), "r"(a3), "r"(b0), "r"(b1));
}

// ---------------- fp32 -> bf16 hi/lo split ----------------
__global__ __launch_bounds__(256) void cvt_x_kernel(const float* __restrict__ x) {
    size_t i = ((size_t)blockIdx.x * 256 + threadIdx.x) * 4;
    float4 v = *(const float4*)(x + i);
    float f[4] = {v.x, v.y, v.z, v.w};
    unsigned short hs[4], ls[4];
    #pragma unroll
    for (int j = 0; j < 4; j++) {
        __nv_bfloat16 h = __float2bfloat16(f[j]);
        float hf = __bfloat162float(h);
        __nv_bfloat16 l = __float2bfloat16(f[j] - hf);
        hs[j] = __bfloat16_as_ushort(h);
        ls[j] = __bfloat16_as_ushort(l);
    }
    uint2 ph, pl;
    ph.x = (unsigned)hs[0] | ((unsigned)hs[1] << 16);
    ph.y = (unsigned)hs[2] | ((unsigned)hs[3] << 16);
    pl.x = (unsigned)ls[0] | ((unsigned)ls[1] << 16);
    pl.y = (unsigned)ls[2] | ((unsigned)ls[3] << 16);
    *(uint2*)(g_xh + i) = ph;
    *(uint2*)(g_xl + i) = pl;
}

__global__ __launch_bounds__(256) void cvt_w_kernel(const float* __restrict__ Wq,
                                                    const float* __restrict__ Wk,
                                                    const float* __restrict__ Wv) {
    int i = (blockIdx.x * 256 + threadIdx.x) * 4;
    if (i >= 3 * DIM * DIM) return;
    int z = i >> 16;
    int o = i & 65535;
    const float* W = (z == 0) ? Wq : (z == 1) ? Wk : Wv;
    float4 v = *(const float4*)(W + o);
    float f[4] = {v.x, v.y, v.z, v.w};
    unsigned short hs[4], ls[4];
    #pragma unroll
    for (int j = 0; j < 4; j++) {
        __nv_bfloat16 h = __float2bfloat16(f[j]);
        float hf = __bfloat162float(h);
        __nv_bfloat16 l = __float2bfloat16(f[j] - hf);
        hs[j] = __bfloat16_as_ushort(h);
        ls[j] = __bfloat16_as_ushort(l);
    }
    uint2 ph, pl;
    ph.x = (unsigned)hs[0] | ((unsigned)hs[1] << 16);
    ph.y = (unsigned)hs[2] | ((unsigned)hs[3] << 16);
    pl.x = (unsigned)ls[0] | ((unsigned)ls[1] << 16);
    pl.y = (unsigned)ls[2] | ((unsigned)ls[3] << 16);
    *(uint2*)(&g_wh[z][o]) = ph;
    *(uint2*)(&g_wl[z][o]) = pl;
}

// ---------------- tensor-core GEMM (mma.sync), tile 128x128, 256 thr, 2 CTA/SM ----------------
#define GK 64
#define ASTRIDE 72    // halfwords per A row (64 + 8 pad)
#define BSTRIDE 136   // halfwords per B row (128 + 8 pad)
#define ABUF (128 * ASTRIDE)
#define BBUF (64 * BSTRIDE)

// phase order: 0:(Ah,Wh) 1:(Ah,Wl) 2:(Al,Wh)
__device__ __forceinline__ void g_load_chunk(int s, int buf, int tid, long mbase, int nbase,
                                             const __nv_bfloat16* Whz,
                                             const __nv_bfloat16* Wlz,
                                             __nv_bfloat16* As, __nv_bfloat16* Bs)
{
    int p = s >> 2;
    const __nv_bfloat16* A = (p == 2) ? g_xl : g_xh;
    const __nv_bfloat16* W = (p == 1) ? Wlz : Whz;
    int kc = (s & 3) * GK;
    unsigned abase = (unsigned)__cvta_generic_to_shared(As + buf * ABUF);
    unsigned bbase = (unsigned)__cvta_generic_to_shared(Bs + buf * BBUF);
    #pragma unroll
    for (int i = 0; i < 4; i++) {                 // A: 128 rows x 64 hw = 1024 x 16B
        int lin = tid + i * 256;
        int r = lin >> 3, c8 = lin & 7;
        cp_async16(abase + (unsigned)(r * ASTRIDE + c8 * 8) * 2u,
                   (const void*)(A + (mbase + r) * DIM + kc + c8 * 8));
    }
    #pragma unroll
    for (int i = 0; i < 4; i++) {                 // B: 64 rows x 128 hw = 1024 x 16B
        int lin = tid + i * 256;
        int r = lin >> 4, c8 = lin & 15;
        cp_async16(bbase + (unsigned)(r * BSTRIDE + c8 * 8) * 2u,
                   (const void*)(W + (kc + r) * DIM + nbase + c8 * 8));
    }
    cp_commit();
}

__global__ __launch_bounds__(256, 2) void gemm_qkv_kernel(
    const float* __restrict__ bq, const float* __restrict__ bk, const float* __restrict__ bv)
{
    extern __shared__ __nv_bfloat16 sm[];
    __nv_bfloat16* As = sm;                 // 2 * ABUF
    __nv_bfloat16* Bs = sm + 2 * ABUF;      // 2 * BBUF

    const int z = blockIdx.x;
    const long mbase = (long)blockIdx.y * 128;
    const int nbase = blockIdx.z * 128;
    const float* bias = (z == 0) ? bq : (z == 1) ? bk : bv;
    float* C = (z == 0) ? g_q : (z == 1) ? g_k : g_v;
    const __nv_bfloat16* Whz = g_wh[z];
    const __nv_bfloat16* Wlz = g_wl[z];

    const int tid = threadIdx.x;
    const int warp = tid >> 5, lane = tid & 31;
    const int wm = (warp >> 1) * 32;   // 0..96
    const int wn = (warp & 1) * 64;    // 0 or 64

    float acc[2][8][4];
    #pragma unroll
    for (int i = 0; i < 2; i++)
        #pragma unroll
        for (int j = 0; j < 8; j++)
            #pragma unroll
            for (int c = 0; c < 4; c++) acc[i][j][c] = 0.0f;

    g_load_chunk(0, 0, tid, mbase, nbase, Whz, Wlz, As, Bs);
    int buf = 0;
    for (int s = 0; s < 12; s++) {
        if (s + 1 < 12) {
            g_load_chunk(s + 1, buf ^ 1, tid, mbase, nbase, Whz, Wlz, As, Bs);
            cp_wait1();
        } else {
            cp_wait0();
        }
        __syncthreads();

        unsigned a_base = (unsigned)__cvta_generic_to_shared(As + buf * ABUF);
        unsigned b_base = (unsigned)__cvta_generic_to_shared(Bs + buf * BBUF);

        #pragma unroll
        for (int kk = 0; kk < 4; kk++) {
            unsigned af[2][4];
            #pragma unroll
            for (int mi = 0; mi < 2; mi++) {
                unsigned addr_a = a_base +
                    (unsigned)((wm + mi * 16 + (lane & 15)) * ASTRIDE + kk * 16 + (lane >> 4) * 8) * 2u;
                ldsm_x4(af[mi][0], af[mi][1], af[mi][2], af[mi][3], addr_a);
            }
            #pragma unroll
            for (int nt = 0; nt < 4; nt++) {
                unsigned b0, b1, b2, b3;
                unsigned addr_b = b_base +
                    (unsigned)((kk * 16 + (lane & 15)) * BSTRIDE + wn + nt * 16 + (lane >> 4) * 8) * 2u;
                ldsm_x4_trans(b0, b1, b2, b3, addr_b);
                #pragma unroll
                for (int mi = 0; mi < 2; mi++) {
                    mma_bf16(acc[mi][nt * 2],     af[mi][0], af[mi][1], af[mi][2], af[mi][3], b0, b1);
                    mma_bf16(acc[mi][nt * 2 + 1], af[mi][0], af[mi][1], af[mi][2], af[mi][3], b2, b3);
                }
            }
        }
        __syncthreads();
        buf ^= 1;
    }

    // epilogue
    #pragma unroll
    for (int mi = 0; mi < 2; mi++) {
        long row0 = mbase + wm + mi * 16 + (lane >> 2);
        #pragma unroll
        for (int n8 = 0; n8 < 8; n8++) {
            int col = nbase + wn + n8 * 8 + (lane & 3) * 2;
            float2 o0, o1;
            o0.x = acc[mi][n8][0] + bias[col];
            o0.y = acc[mi][n8][1] + bias[col + 1];
            o1.x = acc[mi][n8][2] + bias[col];
            o1.y = acc[mi][n8][3] + bias[col + 1];
            *(float2*)&C[row0 * DIM + col] = o0;
            *(float2*)&C[(row0 + 8) * DIM + col] = o1;
        }
    }
}

// ---------------- fused multi-scale window attention (span=64, 2-phase, no shfl) ----------------
#define ASP   64
#define AROWS 67
#define ASTR  65

__device__ __forceinline__ int mirror_row(int o, int sbase) {
    if (o < 0) o = -o;
    if (o >= TSEQ) o = 2 * TSEQ - 2 - o;
    int r = o - sbase;
    if (r < 0) r = 0;
    if (r > AROWS - 1) r = AROWS - 1;
    return r;
}

// phase A: one lane = one (window, query-row); emits 4 softmax weights + count weight
template <int KS>
__device__ __forceinline__ void attn_scores(const float* __restrict__ qs,
                                            const float* __restrict__ ksm,
                                            float* __restrict__ aout,
                                            int wg, int iq, int sbase, int Ts, bool active)
{
    const int l0 = wg * 4;
    const int lq = l0 + iq;

    int rq[KS];
    #pragma unroll
    for (int rr = 0; rr < KS; rr++)
        rq[rr] = mirror_row(lq * KS + rr - KS / 2, sbase);

    int rk[4][KS];
    bool kval[4];
    #pragma unroll
    for (int j = 0; j < 4; j++) {
        kval[j] = (l0 + j) < Ts;
        #pragma unroll
        for (int rr = 0; rr < KS; rr++)
            rk[j][rr] = mirror_row((l0 + j) * KS + rr - KS / 2, sbase);
    }

    float s[4] = {0.f, 0.f, 0.f, 0.f};
    #pragma unroll 4
    for (int d = 0; d < HD; d++) {
        float qd = 0.f;
        #pragma unroll
        for (int rr = 0; rr < KS; rr++) qd += qs[rq[rr] * ASTR + d];
        #pragma unroll
        for (int j = 0; j < 4; j++) {
            float kd = 0.f;
            #pragma unroll
            for (int rr = 0; rr < KS; rr++) kd += ksm[rk[j][rr] * ASTR + d];
            s[j] += qd * kd;
        }
    }
    const float cs = 0.125f / (float)(KS * KS);
    #pragma unroll
    for (int j = 0; j < 4; j++)
        s[j] = kval[j] ? s[j] * cs : 0.0f;   // zero-padded keys score exactly 0

    float mx = fmaxf(fmaxf(s[0], s[1]), fmaxf(s[2], s[3]));
    float e0 = expf(s[0] - mx), e1 = expf(s[1] - mx);
    float e2 = expf(s[2] - mx), e3 = expf(s[3] - mx);
    float inv = (1.0f / (float)KS) / (e0 + e1 + e2 + e3);
    aout[0] = kval[0] ? e0 * inv : 0.f;
    aout[1] = kval[1] ? e1 * inv : 0.f;
    aout[2] = kval[2] ? e2 * inv : 0.f;
    aout[3] = kval[3] ? e3 * inv : 0.f;

    float wgt = 0.0f;
    if (active && lq < Ts) {
        int cnt = (TSEQ * (lq + 1) + Ts - 1) / Ts - (TSEQ * lq + Ts - 1) / Ts;
        wgt = (float)cnt;
    }
    aout[4] = wgt;
}

// phase B: lane owns dims (lane, lane+32); loops rows; no shuffles
template <int KS>
__device__ __forceinline__ void attn_out(const float* __restrict__ vs,
                                         const float* __restrict__ aw,
                                         int wg0, int sbase, int lane,
                                         float& acc0, float& acc1)
{
    for (int rl = 0; rl < 32; rl++) {
        float wgt = aw[rl * 8 + 4];
        if (wgt == 0.0f) continue;
        float a[4];
        a[0] = aw[rl * 8 + 0]; a[1] = aw[rl * 8 + 1];
        a[2] = aw[rl * 8 + 2]; a[3] = aw[rl * 8 + 3];
        const int l0 = (wg0 + (rl >> 2)) * 4;
        float o0 = 0.f, o1 = 0.f;
        #pragma unroll
        for (int j = 0; j < 4; j++) {
            float v0 = 0.f, v1 = 0.f;
            #pragma unroll
            for (int rr = 0; rr < KS; rr++) {
                int r = mirror_row((l0 + j) * KS + rr - KS / 2, sbase);
                v0 += vs[r * ASTR + lane];
                v1 += vs[r * ASTR + lane + 32];
            }
            o0 += a[j] * v0;
            o1 += a[j] * v1;
        }
        float g0 = 0.5f * o0 * (1.0f + erff(o0 * 0.70710678118f));
        float g1 = 0.5f * o1 * (1.0f + erff(o1 * 0.70710678118f));
        acc0 += wgt * g0;
        acc1 += wgt * g1;
    }
}

__global__ __launch_bounds__(128) void attn2_kernel()
{
    extern __shared__ float smf[];
    float* qs   = smf;
    float* ksm  = smf + AROWS * ASTR;
    float* vsm  = smf + 2 * AROWS * ASTR;
    float* aw   = smf + 3 * AROWS * ASTR;          // [4][32][8]
    float* accw = aw + 4 * 32 * 8;                 // [4][64]

    const int tid = threadIdx.x;
    const int bi = blockIdx.x;     // span 0..64 (64 = ragged tail)
    const int b  = blockIdx.y;
    const int h  = blockIdx.z;
    const int sbase = bi * ASP - 3;
    const long gbase = (long)b * TSEQ * DIM + h * HD;

    const float* gq = g_q + gbase;
    const float* gk = g_k + gbase;
    const float* gv = g_v + gbase;

    for (int idx = tid; idx < 3 * AROWS * 16; idx += 128) {
        int t = idx / (AROWS * 16);
        int rem = idx - t * (AROWS * 16);
        int r = rem >> 4;
        int c4 = (rem & 15) * 4;
        int o = sbase + r;
        if (o < 0) o = -o;
        if (o >= TSEQ) o = 2 * TSEQ - 2 - o;
        const float* src = (t == 0 ? gq : t == 1 ? gk : gv) + (long)o * DIM + c4;
        float4 v = *(const float4*)src;
        float* dst = (t == 0 ? qs : t == 1 ? ksm : vsm) + r * ASTR + c4;
        dst[0] = v.x; dst[1] = v.y; dst[2] = v.z; dst[3] = v.w;
    }
    __syncthreads();

    const int warp = tid >> 5;
    const int lane = tid & 31;
    const int wl = lane >> 2;
    const int iq = lane & 3;
    float* ap = aw + (warp * 32 + lane) * 8;

    int wg0;
    if (warp == 0)      { wg0 = bi * 16;     attn_scores<1>(qs, ksm, ap, wg0 + wl, iq, sbase, TSEQ, (wg0 + wl) * 4 < TSEQ); }
    else if (warp == 1) { wg0 = bi * 16 + 8; attn_scores<1>(qs, ksm, ap, wg0 + wl, iq, sbase, TSEQ, (wg0 + wl) * 4 < TSEQ); }
    else if (warp == 2) { wg0 = bi * 8;      attn_scores<2>(qs, ksm, ap, wg0 + wl, iq, sbase, 2049, (wg0 + wl) * 4 < 2049); }
    else                { wg0 = bi * 4;      attn_scores<4>(qs, ksm, ap, wg0 + wl, iq, sbase, 1025, (wl < 4) && ((wg0 + wl) * 4 < 1025)); }
    __syncwarp();

    float acc0 = 0.f, acc1 = 0.f;
    const float* awp = aw + warp * 32 * 8;
    if (warp < 2)       attn_out<1>(vsm, awp, wg0, sbase, lane, acc0, acc1);
    else if (warp == 2) attn_out<2>(vsm, awp, wg0, sbase, lane, acc0, acc1);
    else                attn_out<4>(vsm, awp, wg0, sbase, lane, acc0, acc1);

    accw[warp * HD + lane] = acc0;
    accw[warp * HD + lane + 32] = acc1;
    __syncthreads();

    if (tid < HD) {
        float s = accw[tid] + accw[HD + tid] + accw[2 * HD + tid] + accw[3 * HD + tid];
        atomicAdd(&g_acc[b * DIM + h * HD + tid], s);
    }
}

// ---------------- classifier ----------------
__global__ __launch_bounds__(256) void classifier_kernel(
    const float* __restrict__ Wp,  const float* __restrict__ bp,
    const float* __restrict__ Wc1, const float* __restrict__ bc1,
    const float* __restrict__ Wc2, const float* __restrict__ bc2,
    float* __restrict__ out)
{
    __shared__ float m[DIM], fm[DIM], hbuf[DIM];
    const int b = blockIdx.x;
    const int t = threadIdx.x;

    m[t] = g_acc[b * DIM + t] * (1.0f / (float)TSEQ);
    __syncthreads();

    float a = bp[t];
    for (int k = 0; k < DIM; k++) a += m[k] * Wp[k * DIM + t];
    fm[t] = a;
    __syncthreads();

    float a2 = bc1[t];
    for (int k = 0; k < DIM; k++) a2 += fm[k] * Wc1[k * DIM + t];
    hbuf[t] = fmaxf(a2, 0.0f);
    __syncthreads();

    if (t < 7) {
        float a3 = bc2[t];
        for (int k = 0; k < DIM; k++) a3 += hbuf[k] * Wc2[k * 7 + t];
        out[b * 7 + t] = a3;
    }
}

// ---------------- launch ----------------
extern "C" void kernel_launch(void* const* d_in, const int* in_sizes, int n_in,
                              void* d_out, int out_size)
{
    const float* x   = (const float*)d_in[0];
    const float* Wq  = (const float*)d_in[1];
    const float* bq  = (const float*)d_in[2];
    const float* Wk  = (const float*)d_in[3];
    const float* bk  = (const float*)d_in[4];
    const float* Wv  = (const float*)d_in[5];
    const float* bv  = (const float*)d_in[6];
    const float* Wp  = (const float*)d_in[7];
    const float* bp  = (const float*)d_in[8];
    const float* Wc1 = (const float*)d_in[9];
    const float* bc1 = (const float*)d_in[10];
    const float* Wc2 = (const float*)d_in[11];
    const float* bc2 = (const float*)d_in[12];
    float* out = (float*)d_out;

    const int gsmem = (2 * ABUF + 2 * BBUF) * (int)sizeof(__nv_bfloat16);
    const int asmem = (3 * AROWS * ASTR + 4 * 32 * 8 + 4 * HD) * (int)sizeof(float);
    cudaFuncSetAttribute(gemm_qkv_kernel, cudaFuncAttributeMaxDynamicSharedMemorySize, gsmem);
    cudaFuncSetAttribute(attn2_kernel, cudaFuncAttributeMaxDynamicSharedMemorySize, asmem);

    zero_acc_kernel<<<(BATCH * DIM + 255) / 256, 256>>>();

    cvt_x_kernel<<<(int)(((size_t)MTOT * DIM / 4) / 256), 256>>>(x);
    cvt_w_kernel<<<(3 * DIM * DIM / 4 + 255) / 256, 256>>>(Wq, Wk, Wv);

    gemm_qkv_kernel<<<dim3(3, MTOT / 128, 2), 256, gsmem>>>(bq, bk, bv);

    attn2_kernel<<<dim3(65, BATCH, 4), 128, asmem>>>();

    classifier_kernel<<<BATCH, 256>>>(Wp, bp, Wc1, bc1, Wc2, bc2, out);
}

// round 7
// speedup vs baseline: 2.5812x; 1.1954x over previous
#include <cuda_runtime.h>
#include <cuda_bf16.h>
#include <math.h>

#define DIM   256
#define TSEQ  4096
#define BATCH 32
#define HD    64
#define MTOT  (BATCH * TSEQ)   // 131072

// ---------------- device scratch ----------------
__device__ float g_q[(size_t)MTOT * DIM];
__device__ float g_k[(size_t)MTOT * DIM];
__device__ float g_v[(size_t)MTOT * DIM];
__device__ __nv_bfloat16 g_wh[3][DIM * DIM];
__device__ __nv_bfloat16 g_wl[3][DIM * DIM];
__device__ float g_acc[BATCH * DIM];

__global__ void zero_acc_kernel() {
    int i = blockIdx.x * blockDim.x + threadIdx.x;
    if (i < BATCH * DIM) g_acc[i] = 0.0f;
}

// ---------------- asm helpers ----------------
__device__ __forceinline__ void cp_async16(unsigned dst, const void* src) {
    asm volatile("cp.async.cg.shared.global [%0], [%1], 16;" :: "r"(dst), "l"(src));
}
__device__ __forceinline__ void cp_commit() { asm volatile("cp.async.commit_group;"); }
__device__ __forceinline__ void cp_wait1() { asm volatile("cp.async.wait_group 1;"); }
__device__ __forceinline__ void cp_wait0() { asm volatile("cp.async.wait_group 0;"); }
__device__ __forceinline__ void ldsm_x4(unsigned& r0, unsigned& r1, unsigned& r2, unsigned& r3,
                                        unsigned addr) {
    asm volatile("ldmatrix.sync.aligned.m8n8.x4.shared.b16 {%0,%1,%2,%3},[%4];"
                 : "=r"(r0), "=r"(r1), "=r"(r2), "=r"(r3) : "r"(addr));
}
__device__ __forceinline__ void ldsm_x4_trans(unsigned& r0, unsigned& r1, unsigned& r2, unsigned& r3,
                                              unsigned addr) {
    asm volatile("ldmatrix.sync.aligned.m8n8.x4.trans.shared.b16 {%0,%1,%2,%3},[%4];"
                 : "=r"(r0), "=r"(r1), "=r"(r2), "=r"(r3) : "r"(addr));
}
__device__ __forceinline__ void mma_bf16(float* D, unsigned a0, unsigned a1, unsigned a2, unsigned a3,
                                         unsigned b0, unsigned b1) {
    asm volatile("mma.sync.aligned.m16n8k16.row.col.f32.bf16.bf16.f32 "
                 "{%0,%1,%2,%3},{%4,%5,%6,%7},{%8,%9},{%0,%1,%2,%3};"
                 : "+f"(D[0]), "+f"(D[1]), "+f"(D[2]), "+f"(D[3])
                 : "r"(a0), "r"(a1), "r"(a2), "r"(a3), "r"(b0), "r"(b1));
}

// ---------------- W hi/lo split (tiny, stays a separate kernel) ----------------
__global__ __launch_bounds__(256) void cvt_w_kernel(const float* __restrict__ Wq,
                                                    const float* __restrict__ Wk,
                                                    const float* __restrict__ Wv) {
    int i = (blockIdx.x * 256 + threadIdx.x) * 4;
    if (i >= 3 * DIM * DIM) return;
    int z = i >> 16;
    int o = i & 65535;
    const float* W = (z == 0) ? Wq : (z == 1) ? Wk : Wv;
    float4 v = *(const float4*)(W + o);
    float f[4] = {v.x, v.y, v.z, v.w};
    unsigned short hs[4], ls[4];
    #pragma unroll
    for (int j = 0; j < 4; j++) {
        __nv_bfloat16 h = __float2bfloat16(f[j]);
        float hf = __bfloat162float(h);
        __nv_bfloat16 l = __float2bfloat16(f[j] - hf);
        hs[j] = __bfloat16_as_ushort(h);
        ls[j] = __bfloat16_as_ushort(l);
    }
    uint2 ph, pl;
    ph.x = (unsigned)hs[0] | ((unsigned)hs[1] << 16);
    ph.y = (unsigned)hs[2] | ((unsigned)hs[3] << 16);
    pl.x = (unsigned)ls[0] | ((unsigned)ls[1] << 16);
    pl.y = (unsigned)ls[2] | ((unsigned)ls[3] << 16);
    *(uint2*)(&g_wh[z][o]) = ph;
    *(uint2*)(&g_wl[z][o]) = pl;
}

// ---------------- fused convert + tensor-core GEMM ----------------
// C[128,128] tile = sum over 4 K-chunks of (Ah.Wh + Ah.Wl + Al.Wh) + bias
#define ASTRIDE 72    // halfwords per A row (64 + 8 pad)
#define WSTRIDE 136   // halfwords per W row (128 + 8 pad)
// smem (bf16 elems): Ah[128*72], Al[128*72], W[2 stages][2 hl][64*136]
#define AH_OFF 0
#define AL_OFF 9216
#define W_OFF  18432
#define W_STAGE 17408
#define W_HL    8704
#define GSMEM_BYTES ((18432 + 2 * 17408) * 2)   // 106496

__device__ __forceinline__ void g_load_w(int c, int buf, int tid, int nbase,
                                         const __nv_bfloat16* Whz,
                                         const __nv_bfloat16* Wlz,
                                         unsigned sb)
{
    #pragma unroll
    for (int hl = 0; hl < 2; hl++) {
        const __nv_bfloat16* W = hl ? Wlz : Whz;
        unsigned base = sb + (unsigned)(W_OFF + buf * W_STAGE + hl * W_HL) * 2u;
        #pragma unroll
        for (int i = 0; i < 4; i++) {
            int lin = tid + i * 256;
            int r = lin >> 4, c8 = lin & 15;
            cp_async16(base + (unsigned)(r * WSTRIDE + c8 * 8) * 2u,
                       (const void*)(W + (c * 64 + r) * DIM + nbase + c8 * 8));
        }
    }
    cp_commit();
}

__global__ __launch_bounds__(256, 2) void gemm_fused_kernel(
    const float* __restrict__ x,
    const float* __restrict__ bq, const float* __restrict__ bk, const float* __restrict__ bv)
{
    extern __shared__ __nv_bfloat16 sm[];
    const unsigned sb = (unsigned)__cvta_generic_to_shared(sm);

    const int z = blockIdx.x;
    const int nbase = blockIdx.y * 128;
    const long mbase = (long)blockIdx.z * 128;
    const float* bias = (z == 0) ? bq : (z == 1) ? bk : bv;
    float* C = (z == 0) ? g_q : (z == 1) ? g_k : g_v;
    const __nv_bfloat16* Whz = g_wh[z];
    const __nv_bfloat16* Wlz = g_wl[z];

    const int tid = threadIdx.x;
    const int warp = tid >> 5, lane = tid & 31;
    const int wm = (warp >> 1) * 32;   // 0..96
    const int wn = (warp & 1) * 64;    // 0 or 64

    float acc[2][8][4];
    #pragma unroll
    for (int i = 0; i < 2; i++)
        #pragma unroll
        for (int j = 0; j < 8; j++)
            #pragma unroll
            for (int c = 0; c < 4; c++) acc[i][j][c] = 0.0f;

    g_load_w(0, 0, tid, nbase, Whz, Wlz, sb);
    g_load_w(1, 1, tid, nbase, Whz, Wlz, sb);

    for (int c = 0; c < 4; c++) {
        const int buf = c & 1;

        // load x chunk (128 x 64 fp32), split to Ah/Al bf16 in smem
        #pragma unroll
        for (int i = 0; i < 8; i++) {
            int lin = tid + i * 256;
            int r = lin >> 4, c4 = lin & 15;
            float4 v = *(const float4*)(x + (mbase + r) * DIM + c * 64 + c4 * 4);
            float f[4] = {v.x, v.y, v.z, v.w};
            unsigned short hs[4], ls[4];
            #pragma unroll
            for (int j = 0; j < 4; j++) {
                __nv_bfloat16 h = __float2bfloat16(f[j]);
                float hf = __bfloat162float(h);
                __nv_bfloat16 l = __float2bfloat16(f[j] - hf);
                hs[j] = __bfloat16_as_ushort(h);
                ls[j] = __bfloat16_as_ushort(l);
            }
            uint2 ph, pl;
            ph.x = (unsigned)hs[0] | ((unsigned)hs[1] << 16);
            ph.y = (unsigned)hs[2] | ((unsigned)hs[3] << 16);
            pl.x = (unsigned)ls[0] | ((unsigned)ls[1] << 16);
            pl.y = (unsigned)ls[2] | ((unsigned)ls[3] << 16);
            *(uint2*)(sm + AH_OFF + r * ASTRIDE + c4 * 4) = ph;
            *(uint2*)(sm + AL_OFF + r * ASTRIDE + c4 * 4) = pl;
        }

        if (c < 3) cp_wait1(); else cp_wait0();
        __syncthreads();

        const unsigned ah_base = sb + (unsigned)AH_OFF * 2u;
        const unsigned al_base = sb + (unsigned)AL_OFF * 2u;
        const unsigned wh_base = sb + (unsigned)(W_OFF + buf * W_STAGE) * 2u;
        const unsigned wl_base = wh_base + (unsigned)W_HL * 2u;

        #pragma unroll
        for (int kk = 0; kk < 4; kk++) {
            const unsigned arow = (unsigned)((wm + (lane & 15)) * ASTRIDE + kk * 16 + (lane >> 4) * 8) * 2u;
            unsigned ah[2][4], al[2][4];
            ldsm_x4(ah[0][0], ah[0][1], ah[0][2], ah[0][3], ah_base + arow);
            ldsm_x4(ah[1][0], ah[1][1], ah[1][2], ah[1][3], ah_base + arow + (unsigned)(16 * ASTRIDE) * 2u);
            ldsm_x4(al[0][0], al[0][1], al[0][2], al[0][3], al_base + arow);
            ldsm_x4(al[1][0], al[1][1], al[1][2], al[1][3], al_base + arow + (unsigned)(16 * ASTRIDE) * 2u);

            #pragma unroll
            for (int nt = 0; nt < 4; nt++) {
                const unsigned boff =
                    (unsigned)((kk * 16 + (lane & 15)) * WSTRIDE + wn + nt * 16 + (lane >> 4) * 8) * 2u;
                unsigned h0, h1, h2, h3, l0, l1, l2, l3;
                ldsm_x4_trans(h0, h1, h2, h3, wh_base + boff);
                ldsm_x4_trans(l0, l1, l2, l3, wl_base + boff);
                #pragma unroll
                for (int mi = 0; mi < 2; mi++) {
                    mma_bf16(acc[mi][nt * 2],     ah[mi][0], ah[mi][1], ah[mi][2], ah[mi][3], h0, h1);
                    mma_bf16(acc[mi][nt * 2 + 1], ah[mi][0], ah[mi][1], ah[mi][2], ah[mi][3], h2, h3);
                    mma_bf16(acc[mi][nt * 2],     ah[mi][0], ah[mi][1], ah[mi][2], ah[mi][3], l0, l1);
                    mma_bf16(acc[mi][nt * 2 + 1], ah[mi][0], ah[mi][1], ah[mi][2], ah[mi][3], l2, l3);
                    mma_bf16(acc[mi][nt * 2],     al[mi][0], al[mi][1], al[mi][2], al[mi][3], h0, h1);
                    mma_bf16(acc[mi][nt * 2 + 1], al[mi][0], al[mi][1], al[mi][2], al[mi][3], h2, h3);
                }
            }
        }
        __syncthreads();
        if (c + 2 <= 3) g_load_w(c + 2, buf, tid, nbase, Whz, Wlz, sb);
    }

    // epilogue
    #pragma unroll
    for (int mi = 0; mi < 2; mi++) {
        long row0 = mbase + wm + mi * 16 + (lane >> 2);
        #pragma unroll
        for (int n8 = 0; n8 < 8; n8++) {
            int col = nbase + wn + n8 * 8 + (lane & 3) * 2;
            float b0 = __ldg(&bias[col]);
            float b1 = __ldg(&bias[col + 1]);
            float2 o0, o1;
            o0.x = acc[mi][n8][0] + b0;
            o0.y = acc[mi][n8][1] + b1;
            o1.x = acc[mi][n8][2] + b0;
            o1.y = acc[mi][n8][3] + b1;
            *(float2*)&C[row0 * DIM + col] = o0;
            *(float2*)&C[(row0 + 8) * DIM + col] = o1;
        }
    }
}

// ---------------- fused multi-scale window attention (span=32, high occupancy) ----------------
#define ASP   32
#define AROWS 35
#define ASTR  65

__device__ __forceinline__ int mirror_row(int o, int sbase) {
    if (o < 0) o = -o;
    if (o >= TSEQ) o = 2 * TSEQ - 2 - o;
    int r = o - sbase;
    if (r < 0) r = 0;
    if (r > AROWS - 1) r = AROWS - 1;
    return r;
}

template <int KS>
__device__ __forceinline__ void attn_scores(const float* __restrict__ qs,
                                            const float* __restrict__ ksm,
                                            float* __restrict__ aout,
                                            int wg, int iq, int sbase, int Ts, bool active)
{
    const int l0 = wg * 4;
    const int lq = l0 + iq;

    int rq[KS];
    #pragma unroll
    for (int rr = 0; rr < KS; rr++)
        rq[rr] = mirror_row(lq * KS + rr - KS / 2, sbase);

    int rk[4][KS];
    bool kval[4];
    #pragma unroll
    for (int j = 0; j < 4; j++) {
        kval[j] = (l0 + j) < Ts;
        #pragma unroll
        for (int rr = 0; rr < KS; rr++)
            rk[j][rr] = mirror_row((l0 + j) * KS + rr - KS / 2, sbase);
    }

    float s[4] = {0.f, 0.f, 0.f, 0.f};
    #pragma unroll 4
    for (int d = 0; d < HD; d++) {
        float qd = 0.f;
        #pragma unroll
        for (int rr = 0; rr < KS; rr++) qd += qs[rq[rr] * ASTR + d];
        #pragma unroll
        for (int j = 0; j < 4; j++) {
            float kd = 0.f;
            #pragma unroll
            for (int rr = 0; rr < KS; rr++) kd += ksm[rk[j][rr] * ASTR + d];
            s[j] += qd * kd;
        }
    }
    const float cs = 0.125f / (float)(KS * KS);
    #pragma unroll
    for (int j = 0; j < 4; j++)
        s[j] = kval[j] ? s[j] * cs : 0.0f;   // zero-padded keys score exactly 0

    float mx = fmaxf(fmaxf(s[0], s[1]), fmaxf(s[2], s[3]));
    float e0 = expf(s[0] - mx), e1 = expf(s[1] - mx);
    float e2 = expf(s[2] - mx), e3 = expf(s[3] - mx);
    float inv = (1.0f / (float)KS) / (e0 + e1 + e2 + e3);
    aout[0] = kval[0] ? e0 * inv : 0.f;
    aout[1] = kval[1] ? e1 * inv : 0.f;
    aout[2] = kval[2] ? e2 * inv : 0.f;
    aout[3] = kval[3] ? e3 * inv : 0.f;

    float wgt = 0.0f;
    if (active && lq < Ts) {
        int cnt = (TSEQ * (lq + 1) + Ts - 1) / Ts - (TSEQ * lq + Ts - 1) / Ts;
        wgt = (float)cnt;
    }
    aout[4] = wgt;
}

template <int KS>
__device__ __forceinline__ void attn_out(const float* __restrict__ vs,
                                         const float* __restrict__ aw,
                                         int nrows, int wg0, int sbase, int lane,
                                         float& acc0, float& acc1)
{
    for (int rl = 0; rl < nrows; rl++) {
        float wgt = aw[rl * 8 + 4];
        if (wgt == 0.0f) continue;
        float a[4];
        a[0] = aw[rl * 8 + 0]; a[1] = aw[rl * 8 + 1];
        a[2] = aw[rl * 8 + 2]; a[3] = aw[rl * 8 + 3];
        const int l0 = (wg0 + (rl >> 2)) * 4;
        float o0 = 0.f, o1 = 0.f;
        #pragma unroll
        for (int j = 0; j < 4; j++) {
            float v0 = 0.f, v1 = 0.f;
            #pragma unroll
            for (int rr = 0; rr < KS; rr++) {
                int r = mirror_row((l0 + j) * KS + rr - KS / 2, sbase);
                v0 += vs[r * ASTR + lane];
                v1 += vs[r * ASTR + lane + 32];
            }
            o0 += a[j] * v0;
            o1 += a[j] * v1;
        }
        float g0 = 0.5f * o0 * (1.0f + erff(o0 * 0.70710678118f));
        float g1 = 0.5f * o1 * (1.0f + erff(o1 * 0.70710678118f));
        acc0 += wgt * g0;
        acc1 += wgt * g1;
    }
}

__global__ __launch_bounds__(128) void attn3_kernel()
{
    __shared__ float qs[AROWS * ASTR];
    __shared__ float ksm[AROWS * ASTR];
    __shared__ float vsm[AROWS * ASTR];
    __shared__ float aw[56 * 8];      // 32 s1 + 16 s2 + 8 s4 entries
    __shared__ float accw[4 * HD];

    const int tid = threadIdx.x;
    const int h  = blockIdx.x;
    const int bi = blockIdx.y;     // span 0..128 (128 = ragged tail)
    const int b  = blockIdx.z;
    const int sbase = bi * ASP - 3;
    const long gbase = (long)b * TSEQ * DIM + h * HD;

    const float* gq = g_q + gbase;
    const float* gk = g_k + gbase;
    const float* gv = g_v + gbase;

    for (int idx = tid; idx < 3 * AROWS * 16; idx += 128) {
        int t = idx / (AROWS * 16);
        int rem = idx - t * (AROWS * 16);
        int r = rem >> 4;
        int c4 = (rem & 15) * 4;
        int o = sbase + r;
        if (o < 0) o = -o;
        if (o >= TSEQ) o = 2 * TSEQ - 2 - o;
        const float* src = (t == 0 ? gq : t == 1 ? gk : gv) + (long)o * DIM + c4;
        float4 v = *(const float4*)src;
        float* dst = (t == 0 ? qs : t == 1 ? ksm : vsm) + r * ASTR + c4;
        dst[0] = v.x; dst[1] = v.y; dst[2] = v.z; dst[3] = v.w;
    }
    __syncthreads();

    const int warp = tid >> 5;
    const int lane = tid & 31;

    // phase A: warp 0 = scale1 (32 q); warp 1 = scale2 (lanes 0-15) + scale4 (lanes 16-23)
    if (warp == 0) {
        int wl = lane >> 2, iq = lane & 3;
        attn_scores<1>(qs, ksm, aw + lane * 8, bi * 8 + wl, iq, sbase, TSEQ,
                       (bi * 8 + wl) * 4 < TSEQ);
    } else if (warp == 1) {
        if (lane < 16) {
            int wl = lane >> 2, iq = lane & 3;
            attn_scores<2>(qs, ksm, aw + (32 + lane) * 8, bi * 4 + wl, iq, sbase, 2049, true);
        } else if (lane < 24) {
            int ll = lane - 16;
            int wl = ll >> 2, iq = ll & 3;
            attn_scores<4>(qs, ksm, aw + (48 + ll) * 8, bi * 2 + wl, iq, sbase, 1025, true);
        }
    }
    __syncthreads();

    // phase B: all 4 warps produce outputs
    float acc0 = 0.f, acc1 = 0.f;
    if (warp == 0)      attn_out<1>(vsm, aw,          16, bi * 8,     sbase, lane, acc0, acc1);
    else if (warp == 2) attn_out<1>(vsm, aw + 16 * 8, 16, bi * 8 + 4, sbase, lane, acc0, acc1);
    else if (warp == 1) attn_out<2>(vsm, aw + 32 * 8, 16, bi * 4,     sbase, lane, acc0, acc1);
    else                attn_out<4>(vsm, aw + 48 * 8,  8, bi * 2,     sbase, lane, acc0, acc1);

    accw[warp * HD + lane] = acc0;
    accw[warp * HD + lane + 32] = acc1;
    __syncthreads();

    if (tid < HD) {
        float s = accw[tid] + accw[HD + tid] + accw[2 * HD + tid] + accw[3 * HD + tid];
        atomicAdd(&g_acc[b * DIM + h * HD + tid], s);
    }
}

// ---------------- classifier ----------------
__global__ __launch_bounds__(256) void classifier_kernel(
    const float* __restrict__ Wp,  const float* __restrict__ bp,
    const float* __restrict__ Wc1, const float* __restrict__ bc1,
    const float* __restrict__ Wc2, const float* __restrict__ bc2,
    float* __restrict__ out)
{
    __shared__ float m[DIM], fm[DIM], hbuf[DIM];
    const int b = blockIdx.x;
    const int t = threadIdx.x;

    m[t] = g_acc[b * DIM + t] * (1.0f / (float)TSEQ);
    __syncthreads();

    float a = bp[t];
    for (int k = 0; k < DIM; k++) a += m[k] * Wp[k * DIM + t];
    fm[t] = a;
    __syncthreads();

    float a2 = bc1[t];
    for (int k = 0; k < DIM; k++) a2 += fm[k] * Wc1[k * DIM + t];
    hbuf[t] = fmaxf(a2, 0.0f);
    __syncthreads();

    if (t < 7) {
        float a3 = bc2[t];
        for (int k = 0; k < DIM; k++) a3 += hbuf[k] * Wc2[k * 7 + t];
        out[b * 7 + t] = a3;
    }
}

// ---------------- launch ----------------
extern "C" void kernel_launch(void* const* d_in, const int* in_sizes, int n_in,
                              void* d_out, int out_size)
{
    const float* x   = (const float*)d_in[0];
    const float* Wq  = (const float*)d_in[1];
    const float* bq  = (const float*)d_in[2];
    const float* Wk  = (const float*)d_in[3];
    const float* bk  = (const float*)d_in[4];
    const float* Wv  = (const float*)d_in[5];
    const float* bv  = (const float*)d_in[6];
    const float* Wp  = (const float*)d_in[7];
    const float* bp  = (const float*)d_in[8];
    const float* Wc1 = (const float*)d_in[9];
    const float* bc1 = (const float*)d_in[10];
    const float* Wc2 = (const float*)d_in[11];
    const float* bc2 = (const float*)d_in[12];
    float* out = (float*)d_out;

    cudaFuncSetAttribute(gemm_fused_kernel, cudaFuncAttributeMaxDynamicSharedMemorySize, GSMEM_BYTES);

    zero_acc_kernel<<<(BATCH * DIM + 255) / 256, 256>>>();

    cvt_w_kernel<<<(3 * DIM * DIM / 4 + 255) / 256, 256>>>(Wq, Wk, Wv);

    gemm_fused_kernel<<<dim3(3, 2, MTOT / 128), 256, GSMEM_BYTES>>>(x, bq, bk, bv);

    attn3_kernel<<<dim3(4, 129, BATCH), 128>>>();

    classifier_kernel<<<BATCH, 256>>>(Wp, bp, Wc1, bc1, Wc2, bc2, out);
}